// round 7
// baseline (speedup 1.0000x reference)
#include <cuda_runtime.h>
#include <cstdint>
#include <math.h>

#define BATCH 4
#define CCH   512
#define NSP   4096
#define GROUPS 32
#define GSIZE  65536

static const long CN  = (long)CCH * NSP;
static const long NNL = (long)NSP * NSP;

// Scratch (device globals — allocation-free per harness rules)
__device__ float g_ht[BATCH * CCH * NSP];  // normalized h transposed [B][N][C] (tf32)
__device__ float g_q [BATCH * CCH * NSP];  // q_t [B][N][C] (tf32)
__device__ float g_k [BATCH * CCH * NSP];  // k_t [B][N][C] (tf32)
__device__ float g_v [BATCH * CCH * NSP];  // v   [B][C][N] (tf32)
__device__ float g_o [BATCH * CCH * NSP];  // O_t [B][N][C] (tf32)
__device__ float g_s [BATCH * NSP * NSP];  // scores / attn [B][i][j]
__device__ float g_w [4 * CCH * CCH];      // tf32-rounded wq,wk,wv,wp
__device__ float g_mu [BATCH * GROUPS];
__device__ float g_rsd[BATCH * GROUPS];

// ===========================================================================
// helpers
// ===========================================================================
__device__ __forceinline__ float rtf(float f) {
    uint32_t u;
    asm("cvt.rna.tf32.f32 %0, %1;" : "=r"(u) : "f"(f));
    return __uint_as_float(u);
}
__device__ __forceinline__ uint32_t s2u(const void* p) {
    uint32_t a;
    asm("{ .reg .u64 t; cvta.to.shared.u64 t, %1; cvt.u32.u64 %0, t; }"
        : "=r"(a) : "l"(p));
    return a;
}
__device__ __forceinline__ void cpa16(uint32_t d, const float* s) {
    asm volatile("cp.async.cg.shared.global [%0], [%1], 16;" :: "r"(d), "l"(s));
}
__device__ __forceinline__ void mma8(float* d, const uint32_t* a, const uint32_t* b) {
    asm volatile(
        "mma.sync.aligned.m16n8k8.row.col.f32.tf32.tf32.f32 "
        "{%0,%1,%2,%3}, {%4,%5,%6,%7}, {%8,%9}, {%0,%1,%2,%3};"
        : "+f"(d[0]), "+f"(d[1]), "+f"(d[2]), "+f"(d[3])
        : "r"(a[0]), "r"(a[1]), "r"(a[2]), "r"(a[3]), "r"(b[0]), "r"(b[1]));
}
__device__ __forceinline__ void ldm4(uint32_t* r, uint32_t addr) {
    asm volatile(
        "ldmatrix.sync.aligned.m8n8.x4.shared.b16 {%0,%1,%2,%3}, [%4];"
        : "=r"(r[0]), "=r"(r[1]), "=r"(r[2]), "=r"(r[3]) : "r"(addr));
}

// ===========================================================================
// GroupNorm stats: one block per (b, group); writes mu/rstd only.
// ===========================================================================
__global__ void gn_stats(const float* __restrict__ x,
                         float* __restrict__ mu_out,
                         float* __restrict__ rsd_out)
{
    const int bg  = blockIdx.x;
    const long base = (long)bg * GSIZE;
    const int tid = threadIdx.x;

    float s = 0.f, ss = 0.f;
    for (int i = tid * 4; i < GSIZE; i += 256 * 4) {
        float4 v = *(const float4*)(x + base + i);
        s  += v.x + v.y + v.z + v.w;
        ss += v.x*v.x + v.y*v.y + v.z*v.z + v.w*v.w;
    }
    __shared__ float rs[256], rq[256];
    rs[tid] = s; rq[tid] = ss;
    __syncthreads();
    for (int o = 128; o > 0; o >>= 1) {
        if (tid < o) { rs[tid] += rs[tid + o]; rq[tid] += rq[tid + o]; }
        __syncthreads();
    }
    if (tid == 0) {
        float mu  = rs[0] * (1.f / GSIZE);
        float var = rq[0] * (1.f / GSIZE) - mu * mu;
        mu_out[bg]  = mu;
        rsd_out[bg] = rsqrtf(var + 1e-6f);
    }
}

// ===========================================================================
// Fused normalize + transpose + tf32-round: x[C,N] -> h_t[N,C]
// ===========================================================================
__global__ void ntrans_kernel(const float* __restrict__ x,
                              const float* __restrict__ gamma,
                              const float* __restrict__ beta,
                              const float* __restrict__ mu,
                              const float* __restrict__ rsd,
                              float* __restrict__ out)
{
    __shared__ float t[32][33];
    const int bz = blockIdx.z;
    const long off = (long)bz * CN;
    const float* I = x + off;
    float* O = out + off;
    const int c0 = blockIdx.y * 32, n0 = blockIdx.x * 32;
    const int tx = threadIdx.x, ty = threadIdx.y;   // (32, 8)
#pragma unroll
    for (int i = 0; i < 32; i += 8) {
        const int c = c0 + ty + i;
        const int bg = bz * GROUPS + (c >> 4);      // 16 channels per group
        const float ga = gamma[c] * rsd[bg];
        const float be = beta[c] - mu[bg] * ga;
        t[ty + i][tx] = I[(long)c * NSP + n0 + tx] * ga + be;
    }
    __syncthreads();
#pragma unroll
    for (int i = 0; i < 32; i += 8)
        O[(long)(n0 + ty + i) * CCH + c0 + tx] = rtf(t[tx][ty + i]);
}

// ===========================================================================
// Round fp32 -> tf32-valued fp32 (weights)
// ===========================================================================
__global__ void round_kernel(const float* __restrict__ in,
                             float* __restrict__ out, int n)
{
    int i = (blockIdx.x * 256 + threadIdx.x) * 4;
    if (i < n) {
        float4 v = *(const float4*)(in + i);
        v.x = rtf(v.x); v.y = rtf(v.y); v.z = rtf(v.z); v.w = rtf(v.w);
        *(float4*)(out + i) = v;
    }
}

// ===========================================================================
// tf32 tensor-core GEMM: mma.sync + ldmatrix + 4-stage cp.async pipeline.
// Operands already tf32-rounded; NO cvt in the loop.
//   D[m,n] = alpha * sum_k A[m*lda+k] * B[n*ldb+k] (+biasM[m]) (+biasN[n]) (+R)
// CTA tile 128x128, K-tile 16, 8 warps (2x4), warp tile 64x32, 256 threads,
// 2 CTAs/SM (16 warps/SM for latency hiding).
// smem row stride 20 floats (80B): conflict-free ldmatrix, 16B aligned.
// 4 stages, issue-ahead 2, single barrier per K-tile.
// Dynamic smem: 4 stages * (128+128) rows * 20 floats * 4B = 81920 B.
// ===========================================================================
#define TG_STAGE   20480u              // (A:10240 + B:10240) per stage
#define TG_SMEM_BYTES 81920

template<bool ROUND_C>
__global__ void __launch_bounds__(256, 2)
tgemm(const float* __restrict__ A, const float* __restrict__ B,
      float* __restrict__ C, int lda, int ldb, int ldc,
      long sA, long sB, long sC, long sR,
      int K, float alpha,
      const float* __restrict__ biasM, const float* __restrict__ biasN,
      const float* __restrict__ res)
{
    extern __shared__ float sm[];
    const uint32_t sbase = s2u(sm);

    const int tid  = threadIdx.x;
    const int lane = tid & 31, wid = tid >> 5;
    const int m0 = blockIdx.y * 128, n0 = blockIdx.x * 128, bz = blockIdx.z;

    const float* Ab = A + bz * sA + (long)m0 * lda;
    const float* Bb = B + bz * sB + (long)n0 * ldb;

    // cp.async staging: 256 threads cover 128 rows x 16 cols twice (rows r0, r0+64)
    const int r0 = tid >> 2;            // 0..63
    const int c4 = (tid & 3) * 4;       // 0,4,8,12
    const uint32_t stDst = (uint32_t)(r0 * 20 + c4) * 4u;
    const float* pA = Ab + (long)r0 * lda + c4;
    const float* pB = Bb + (long)r0 * ldb + c4;
    const long aS = (long)64 * lda;
    const long bS = (long)64 * ldb;

    // warp/fragment addressing: warp grid 2x4, warp tile 64x32
    const int qid = lane >> 2, rid = lane & 3;
    const int mw = (wid >> 2) * 64, nw = (wid & 3) * 32;
    const uint32_t aLD = sbase + (uint32_t)(mw + (lane & 15)) * 80u
                       + (uint32_t)(lane >> 4) * 16u;
    const uint32_t bLD = sbase + 10240u + (uint32_t)(nw + (lane & 7)) * 80u
                       + (uint32_t)(lane >> 3) * 16u;

    float d[4][4][4];
#pragma unroll
    for (int i = 0; i < 4; i++)
#pragma unroll
        for (int j = 0; j < 4; j++)
#pragma unroll
            for (int l = 0; l < 4; l++) d[i][j][l] = 0.f;

    const int NK = K >> 4;

    // prologue: stages 0,1
#pragma unroll
    for (int p = 0; p < 2; p++) {
        const uint32_t ao = sbase + (uint32_t)p * TG_STAGE + stDst;
        const float* qa = pA + p * 16;
        const float* qb = pB + p * 16;
        cpa16(ao,                   qa);
        cpa16(ao + 5120u,           qa + aS);     // +64 rows * 80B
        cpa16(ao + 10240u,          qb);
        cpa16(ao + 10240u + 5120u,  qb + bS);
        asm volatile("cp.async.commit_group;" ::: "memory");
    }

#pragma unroll 1
    for (int kt = 0; kt < NK; kt++) {
        const uint32_t bufo = (uint32_t)(kt & 3) * TG_STAGE;

        asm volatile("cp.async.wait_group 1;" ::: "memory");
        __syncthreads();

        // fragments: 4 B-ldm.x4 + 8 A-ldm.x4, no cvt (pre-rounded data)
        uint32_t bf[4][4], af[2][4][4];
#pragma unroll
        for (int ni = 0; ni < 4; ni++)
            ldm4(bf[ni], bLD + bufo + (uint32_t)ni * 640u);
#pragma unroll
        for (int ks = 0; ks < 2; ks++)
#pragma unroll
            for (int mi = 0; mi < 4; mi++)
                ldm4(af[ks][mi], aLD + bufo + (uint32_t)mi * 1280u
                                      + (uint32_t)ks * 32u);

        // issue loads for kt+2
        if (kt + 2 < NK) {
            const uint32_t ao = sbase + (uint32_t)((kt + 2) & 3) * TG_STAGE + stDst;
            const float* qa = pA + (kt + 2) * 16;
            const float* qb = pB + (kt + 2) * 16;
            cpa16(ao,                  qa);
            cpa16(ao + 5120u,          qa + aS);
            cpa16(ao + 10240u,         qb);
            cpa16(ao + 10240u + 5120u, qb + bS);
        }
        asm volatile("cp.async.commit_group;" ::: "memory");

#pragma unroll
        for (int ks = 0; ks < 2; ks++)
#pragma unroll
            for (int mi = 0; mi < 4; mi++)
#pragma unroll
                for (int ni = 0; ni < 4; ni++)
                    mma8(d[mi][ni], af[ks][mi], &bf[ni][ks * 2]);
        // no trailing barrier: 4 stages + issue-ahead 2 + top barrier => safe
    }

    // epilogue: coalesced float2 stores
    float* Cb = C + bz * sC;
    const float* Rb = res ? (res + bz * sR) : nullptr;
#pragma unroll
    for (int mi = 0; mi < 4; mi++) {
        const int rA = m0 + mw + mi * 16 + qid;
        const int rB = rA + 8;
        const float bmA = biasM ? biasM[rA] : 0.f;
        const float bmB = biasM ? biasM[rB] : 0.f;
#pragma unroll
        for (int ni = 0; ni < 4; ni++) {
            const int col = n0 + nw + ni * 8 + rid * 2;
            float bn0 = 0.f, bn1 = 0.f;
            if (biasN) { bn0 = biasN[col]; bn1 = biasN[col + 1]; }
            float2 v0, v1;
            v0.x = d[mi][ni][0] * alpha + bmA + bn0;
            v0.y = d[mi][ni][1] * alpha + bmA + bn1;
            v1.x = d[mi][ni][2] * alpha + bmB + bn0;
            v1.y = d[mi][ni][3] * alpha + bmB + bn1;
            const long o0 = (long)rA * ldc + col;
            const long o1 = (long)rB * ldc + col;
            if (Rb) {
                float2 ra = *(const float2*)(Rb + o0);
                float2 rb = *(const float2*)(Rb + o1);
                v0.x += ra.x; v0.y += ra.y;
                v1.x += rb.x; v1.y += rb.y;
            }
            if (ROUND_C) {
                v0.x = rtf(v0.x); v0.y = rtf(v0.y);
                v1.x = rtf(v1.x); v1.y = rtf(v1.y);
            }
            *(float2*)(Cb + o0) = v0;
            *(float2*)(Cb + o1) = v1;
        }
    }
}

// ===========================================================================
// Row softmax over 4096 columns; output rounded to tf32 (feeds PV GEMM).
// ===========================================================================
__global__ void softmax_kernel(float* __restrict__ s)
{
    const long row = blockIdx.x;
    float* p = s + row * (long)NSP;
    const int tid = threadIdx.x;

    __shared__ float buf[NSP];
    __shared__ float red[256];

    float m = -1e30f;
    for (int i = tid * 4; i < NSP; i += 1024) {
        float4 v = *(const float4*)(p + i);
        *(float4*)(buf + i) = v;
        m = fmaxf(m, fmaxf(fmaxf(v.x, v.y), fmaxf(v.z, v.w)));
    }
    red[tid] = m;
    __syncthreads();
    for (int o = 128; o > 0; o >>= 1) {
        if (tid < o) red[tid] = fmaxf(red[tid], red[tid + o]);
        __syncthreads();
    }
    m = red[0];
    __syncthreads();

    float sum = 0.f;
    for (int i = tid * 4; i < NSP; i += 1024) {
        float4 v = *(const float4*)(buf + i);
        v.x = __expf(v.x - m);
        v.y = __expf(v.y - m);
        v.z = __expf(v.z - m);
        v.w = __expf(v.w - m);
        *(float4*)(buf + i) = v;
        sum += v.x + v.y + v.z + v.w;
    }
    red[tid] = sum;
    __syncthreads();
    for (int o = 128; o > 0; o >>= 1) {
        if (tid < o) red[tid] += red[tid + o];
        __syncthreads();
    }
    const float inv = 1.f / red[0];

    for (int i = tid * 4; i < NSP; i += 1024) {
        float4 v = *(const float4*)(buf + i);
        v.x = rtf(v.x * inv); v.y = rtf(v.y * inv);
        v.z = rtf(v.z * inv); v.w = rtf(v.w * inv);
        *(float4*)(p + i) = v;
    }
}

// ===========================================================================
extern "C" void kernel_launch(void* const* d_in, const int* in_sizes, int n_in,
                              void* d_out, int out_size)
{
    const float* x     = (const float*)d_in[0];
    const float* gamma = (const float*)d_in[1];
    const float* beta  = (const float*)d_in[2];
    const float* wq    = (const float*)d_in[3];
    const float* bq    = (const float*)d_in[4];
    const float* wk    = (const float*)d_in[5];
    const float* bk    = (const float*)d_in[6];
    const float* wv    = (const float*)d_in[7];
    const float* bv    = (const float*)d_in[8];
    const float* wp    = (const float*)d_in[9];
    const float* bp    = (const float*)d_in[10];
    float* out = (float*)d_out;

    float *pht, *pq, *pk, *pv, *po, *ps, *pw, *pmu, *prs;
    cudaGetSymbolAddress((void**)&pht, g_ht);
    cudaGetSymbolAddress((void**)&pq,  g_q);
    cudaGetSymbolAddress((void**)&pk,  g_k);
    cudaGetSymbolAddress((void**)&pv,  g_v);
    cudaGetSymbolAddress((void**)&po,  g_o);
    cudaGetSymbolAddress((void**)&ps,  g_s);
    cudaGetSymbolAddress((void**)&pw,  g_w);
    cudaGetSymbolAddress((void**)&pmu, g_mu);
    cudaGetSymbolAddress((void**)&prs, g_rsd);

    cudaFuncSetAttribute(tgemm<true>,  cudaFuncAttributeMaxDynamicSharedMemorySize,
                         TG_SMEM_BYTES);
    cudaFuncSetAttribute(tgemm<false>, cudaFuncAttributeMaxDynamicSharedMemorySize,
                         TG_SMEM_BYTES);

    const int WN = CCH * CCH;           // 262144
    float* rwq = pw;
    float* rwk = pw + WN;
    float* rwv = pw + 2 * WN;
    float* rwp = pw + 3 * WN;

    // 0) tf32-round the weight matrices
    round_kernel<<<WN / 1024, 256>>>(wq, rwq, WN);
    round_kernel<<<WN / 1024, 256>>>(wk, rwk, WN);
    round_kernel<<<WN / 1024, 256>>>(wv, rwv, WN);
    round_kernel<<<WN / 1024, 256>>>(wp, rwp, WN);

    // 1) GroupNorm stats
    gn_stats<<<BATCH * GROUPS, 256>>>(x, pmu, prs);

    // 2) fused normalize + transpose -> h_t [N,C] (tf32)
    dim3 gT(NSP / 32, CCH / 32, BATCH);
    ntrans_kernel<<<gT, dim3(32, 8)>>>(x, gamma, beta, pmu, prs, pht);

    // 3) q_t[i,o] = sum_c h_t[i,c] wq[o,c] + bq[o]   (M=NSP, N=CCH)
    dim3 gNC(CCH / 128, NSP / 128, BATCH);   // (4, 32, 4)
    tgemm<true><<<gNC, 256, TG_SMEM_BYTES>>>(pht, rwq, pq, CCH, CCH, CCH,
                                             CN, 0, CN, 0,
                                             CCH, 1.f, nullptr, bq, nullptr);
    tgemm<true><<<gNC, 256, TG_SMEM_BYTES>>>(pht, rwk, pk, CCH, CCH, CCH,
                                             CN, 0, CN, 0,
                                             CCH, 1.f, nullptr, bk, nullptr);

    // 4) v[c,j] = sum_c' wv[c,c'] h_t[j,c'] + bv[c]  (M=CCH, N=NSP)
    dim3 gCN(NSP / 128, CCH / 128, BATCH);   // (32, 4, 4)
    tgemm<true><<<gCN, 256, TG_SMEM_BYTES>>>(rwv, pht, pv, CCH, CCH, NSP,
                                             0, CN, CN, 0,
                                             CCH, 1.f, bv, nullptr, nullptr);

    // 5) scores S[i,j] = scale * sum_c q_t[i,c] k_t[j,c]  (M=N=NSP)
    const float scale = 0.04419417382415922f;  // 512^-0.5
    dim3 gSS(NSP / 128, NSP / 128, BATCH);   // (32, 32, 4)
    tgemm<false><<<gSS, 256, TG_SMEM_BYTES>>>(pq, pk, ps, CCH, CCH, NSP,
                                              CN, CN, NNL, 0,
                                              CCH, scale, nullptr, nullptr, nullptr);

    // 6) softmax over keys (rows of S), rounds output to tf32
    softmax_kernel<<<BATCH * NSP, 256>>>(ps);

    // 7) O_t[i,c] = sum_j P[i,j] v[c,j]   (M=NSP, N=CCH, K=NSP)
    tgemm<true><<<gNC, 256, TG_SMEM_BYTES>>>(ps, pv, po, NSP, NSP, CCH,
                                             NNL, CN, CN, 0,
                                             NSP, 1.f, nullptr, nullptr, nullptr);

    // 8) out[o,n] = sum_c wp[o,c] O_t[n,c] + bp[o] + x[o,n]  (M=CCH, N=NSP)
    tgemm<false><<<gCN, 256, TG_SMEM_BYTES>>>(rwp, po, out, CCH, CCH, NSP,
                                              0, CN, CN, CN,
                                              CCH, 1.f, bp, nullptr, x);
}

// round 8
// speedup vs baseline: 1.1111x; 1.1111x over previous
#include <cuda_runtime.h>
#include <cstdint>
#include <math.h>

#define BATCH 4
#define CCH   512
#define NSP   4096
#define GROUPS 32
#define GSIZE  65536

static const long CN  = (long)CCH * NSP;
static const long NNL = (long)NSP * NSP;

// Scratch (device globals — allocation-free per harness rules)
__device__ float g_ht[BATCH * CCH * NSP];  // normalized h transposed [B][N][C] (tf32)
__device__ float g_q [BATCH * CCH * NSP];  // q_t [B][N][C] (tf32)
__device__ float g_k [BATCH * CCH * NSP];  // k_t [B][N][C] (tf32)
__device__ float g_v [BATCH * CCH * NSP];  // v   [B][C][N] (tf32)
__device__ float g_o [BATCH * CCH * NSP];  // O_t [B][N][C] (tf32)
__device__ float g_s [BATCH * NSP * NSP];  // scores / attn [B][i][j]
__device__ float g_w [4 * CCH * CCH];      // tf32-rounded wq,wk,wv,wp
__device__ float g_mu [BATCH * GROUPS];
__device__ float g_rsd[BATCH * GROUPS];

// ===========================================================================
// helpers
// ===========================================================================
__device__ __forceinline__ float rtf(float f) {
    uint32_t u;
    asm("cvt.rna.tf32.f32 %0, %1;" : "=r"(u) : "f"(f));
    return __uint_as_float(u);
}
__device__ __forceinline__ uint32_t s2u(const void* p) {
    uint32_t a;
    asm("{ .reg .u64 t; cvta.to.shared.u64 t, %1; cvt.u32.u64 %0, t; }"
        : "=r"(a) : "l"(p));
    return a;
}
__device__ __forceinline__ void cpa16(uint32_t d, const float* s) {
    asm volatile("cp.async.cg.shared.global [%0], [%1], 16;" :: "r"(d), "l"(s));
}
__device__ __forceinline__ void mma8(float* d, const uint32_t* a, const uint32_t* b) {
    asm volatile(
        "mma.sync.aligned.m16n8k8.row.col.f32.tf32.tf32.f32 "
        "{%0,%1,%2,%3}, {%4,%5,%6,%7}, {%8,%9}, {%0,%1,%2,%3};"
        : "+f"(d[0]), "+f"(d[1]), "+f"(d[2]), "+f"(d[3])
        : "r"(a[0]), "r"(a[1]), "r"(a[2]), "r"(a[3]), "r"(b[0]), "r"(b[1]));
}
__device__ __forceinline__ void ldm4(uint32_t* r, uint32_t addr) {
    asm volatile(
        "ldmatrix.sync.aligned.m8n8.x4.shared.b16 {%0,%1,%2,%3}, [%4];"
        : "=r"(r[0]), "=r"(r[1]), "=r"(r[2]), "=r"(r[3]) : "r"(addr));
}

// ===========================================================================
// GroupNorm stats: one block per (b, group); writes mu/rstd only.
// ===========================================================================
__global__ void gn_stats(const float* __restrict__ x,
                         float* __restrict__ mu_out,
                         float* __restrict__ rsd_out)
{
    const int bg  = blockIdx.x;
    const long base = (long)bg * GSIZE;
    const int tid = threadIdx.x;

    float s = 0.f, ss = 0.f;
    for (int i = tid * 4; i < GSIZE; i += 256 * 4) {
        float4 v = *(const float4*)(x + base + i);
        s  += v.x + v.y + v.z + v.w;
        ss += v.x*v.x + v.y*v.y + v.z*v.z + v.w*v.w;
    }
    __shared__ float rs[256], rq[256];
    rs[tid] = s; rq[tid] = ss;
    __syncthreads();
    for (int o = 128; o > 0; o >>= 1) {
        if (tid < o) { rs[tid] += rs[tid + o]; rq[tid] += rq[tid + o]; }
        __syncthreads();
    }
    if (tid == 0) {
        float mu  = rs[0] * (1.f / GSIZE);
        float var = rq[0] * (1.f / GSIZE) - mu * mu;
        mu_out[bg]  = mu;
        rsd_out[bg] = rsqrtf(var + 1e-6f);
    }
}

// ===========================================================================
// Fused normalize + transpose + tf32-round: x[C,N] -> h_t[N,C]
// ===========================================================================
__global__ void ntrans_kernel(const float* __restrict__ x,
                              const float* __restrict__ gamma,
                              const float* __restrict__ beta,
                              const float* __restrict__ mu,
                              const float* __restrict__ rsd,
                              float* __restrict__ out)
{
    __shared__ float t[32][33];
    const int bz = blockIdx.z;
    const long off = (long)bz * CN;
    const float* I = x + off;
    float* O = out + off;
    const int c0 = blockIdx.y * 32, n0 = blockIdx.x * 32;
    const int tx = threadIdx.x, ty = threadIdx.y;   // (32, 8)
#pragma unroll
    for (int i = 0; i < 32; i += 8) {
        const int c = c0 + ty + i;
        const int bg = bz * GROUPS + (c >> 4);      // 16 channels per group
        const float ga = gamma[c] * rsd[bg];
        const float be = beta[c] - mu[bg] * ga;
        t[ty + i][tx] = I[(long)c * NSP + n0 + tx] * ga + be;
    }
    __syncthreads();
#pragma unroll
    for (int i = 0; i < 32; i += 8)
        O[(long)(n0 + ty + i) * CCH + c0 + tx] = rtf(t[tx][ty + i]);
}

// ===========================================================================
// Round fp32 -> tf32-valued fp32 (weights)
// ===========================================================================
__global__ void round_kernel(const float* __restrict__ in,
                             float* __restrict__ out, int n)
{
    int i = (blockIdx.x * 256 + threadIdx.x) * 4;
    if (i < n) {
        float4 v = *(const float4*)(in + i);
        v.x = rtf(v.x); v.y = rtf(v.y); v.z = rtf(v.z); v.w = rtf(v.w);
        *(float4*)(out + i) = v;
    }
}

// ===========================================================================
// tf32 tensor-core GEMM: mma.sync + ldmatrix + 4-stage cp.async pipeline.
// Operands already tf32-rounded; NO cvt in the loop. (Round-6 winning shape.)
//   D[m,n] = alpha * sum_k A[m*lda+k] * B[n*ldb+k] (+biasM[m]) (+biasN[n]) (+R)
// CTA tile 128x128, K-tile 16, 4 warps (2x2), warp tile 64x64, 128 threads,
// 2 CTAs/SM. smem row stride 20 floats (80B): conflict-free ldmatrix.
// 4 stages, issue-ahead 2, single barrier per K-tile.
// Dynamic smem: 4 stages * (128+128) rows * 20 floats * 4B = 81920 B.
// ===========================================================================
#define TG_STAGE   20480u              // (A:10240 + B:10240) per stage
#define TG_SMEM_BYTES 81920

template<bool ROUND_C>
__global__ void __launch_bounds__(128, 2)
tgemm(const float* __restrict__ A, const float* __restrict__ B,
      float* __restrict__ C, int lda, int ldb, int ldc,
      long sA, long sB, long sC, long sR,
      int K, float alpha,
      const float* __restrict__ biasM, const float* __restrict__ biasN,
      const float* __restrict__ res)
{
    extern __shared__ float sm[];
    const uint32_t sbase = s2u(sm);

    const int tid  = threadIdx.x;
    const int lane = tid & 31, wid = tid >> 5;
    const int m0 = blockIdx.y * 128, n0 = blockIdx.x * 128, bz = blockIdx.z;

    const float* Ab = A + bz * sA + (long)m0 * lda;
    const float* Bb = B + bz * sB + (long)n0 * ldb;

    // cp.async staging: thread covers rows r0+{0,32,64,96}, 16B chunk c4
    const int r0 = tid >> 2;            // 0..31
    const int c4 = (tid & 3) * 4;       // 0,4,8,12
    const uint32_t stDst = (uint32_t)(r0 * 20 + c4) * 4u;
    const float* pA = Ab + (long)r0 * lda + c4;
    const float* pB = Bb + (long)r0 * ldb + c4;
    const long aS = (long)32 * lda;
    const long bS = (long)32 * ldb;

    // warp/fragment addressing: warp grid 2x2, warp tile 64x64
    const int qid = lane >> 2, rid = lane & 3;
    const int mw = (wid >> 1) * 64, nw = (wid & 1) * 64;
    const uint32_t aLD = sbase + (uint32_t)(mw + (lane & 15)) * 80u
                       + (uint32_t)(lane >> 4) * 16u;
    const uint32_t bLD = sbase + 10240u + (uint32_t)(nw + (lane & 7)) * 80u
                       + (uint32_t)(lane >> 3) * 16u;

    float d[4][8][4];
#pragma unroll
    for (int i = 0; i < 4; i++)
#pragma unroll
        for (int j = 0; j < 8; j++)
#pragma unroll
            for (int l = 0; l < 4; l++) d[i][j][l] = 0.f;

    const int NK = K >> 4;

    // prologue: stages 0,1
#pragma unroll
    for (int p = 0; p < 2; p++) {
        const uint32_t ao = sbase + (uint32_t)p * TG_STAGE + stDst;
        const float* qa = pA + p * 16;
        const float* qb = pB + p * 16;
#pragma unroll
        for (int i = 0; i < 4; i++) {
            cpa16(ao + (uint32_t)i * 2560u, qa + i * aS);
            cpa16(ao + 10240u + (uint32_t)i * 2560u, qb + i * bS);
        }
        asm volatile("cp.async.commit_group;" ::: "memory");
    }

#pragma unroll 1
    for (int kt = 0; kt < NK; kt++) {
        const uint32_t bufo = (uint32_t)(kt & 3) * TG_STAGE;

        asm volatile("cp.async.wait_group 1;" ::: "memory");
        __syncthreads();

        // all fragments up front: 8 B-ldm + 8 A-ldm, no cvt (pre-rounded data)
        uint32_t bf[8][4], af[2][4][4];
#pragma unroll
        for (int ni = 0; ni < 8; ni++)
            ldm4(bf[ni], bLD + bufo + (uint32_t)ni * 640u);
#pragma unroll
        for (int ks = 0; ks < 2; ks++)
#pragma unroll
            for (int mi = 0; mi < 4; mi++)
                ldm4(af[ks][mi], aLD + bufo + (uint32_t)mi * 1280u
                                      + (uint32_t)ks * 32u);

        // issue loads for kt+2 (after ldm so LSU issue doesn't delay them)
        if (kt + 2 < NK) {
            const uint32_t ao = sbase + (uint32_t)((kt + 2) & 3) * TG_STAGE + stDst;
            const float* qa = pA + (kt + 2) * 16;
            const float* qb = pB + (kt + 2) * 16;
#pragma unroll
            for (int i = 0; i < 4; i++) {
                cpa16(ao + (uint32_t)i * 2560u, qa + i * aS);
                cpa16(ao + 10240u + (uint32_t)i * 2560u, qb + i * bS);
            }
        }
        asm volatile("cp.async.commit_group;" ::: "memory");

#pragma unroll
        for (int ks = 0; ks < 2; ks++)
#pragma unroll
            for (int mi = 0; mi < 4; mi++)
#pragma unroll
                for (int ni = 0; ni < 8; ni++)
                    mma8(d[mi][ni], af[ks][mi], &bf[ni][ks * 2]);
        // no trailing barrier: 4 stages + issue-ahead 2 + top barrier => safe
    }

    // epilogue: coalesced float2 stores
    float* Cb = C + bz * sC;
    const float* Rb = res ? (res + bz * sR) : nullptr;
#pragma unroll
    for (int mi = 0; mi < 4; mi++) {
        const int rA = m0 + mw + mi * 16 + qid;
        const int rB = rA + 8;
        const float bmA = biasM ? biasM[rA] : 0.f;
        const float bmB = biasM ? biasM[rB] : 0.f;
#pragma unroll
        for (int ni = 0; ni < 8; ni++) {
            const int col = n0 + nw + ni * 8 + rid * 2;
            float bn0 = 0.f, bn1 = 0.f;
            if (biasN) { bn0 = biasN[col]; bn1 = biasN[col + 1]; }
            float2 v0, v1;
            v0.x = d[mi][ni][0] * alpha + bmA + bn0;
            v0.y = d[mi][ni][1] * alpha + bmA + bn1;
            v1.x = d[mi][ni][2] * alpha + bmB + bn0;
            v1.y = d[mi][ni][3] * alpha + bmB + bn1;
            const long o0 = (long)rA * ldc + col;
            const long o1 = (long)rB * ldc + col;
            if (Rb) {
                float2 ra = *(const float2*)(Rb + o0);
                float2 rb = *(const float2*)(Rb + o1);
                v0.x += ra.x; v0.y += ra.y;
                v1.x += rb.x; v1.y += rb.y;
            }
            if (ROUND_C) {
                v0.x = rtf(v0.x); v0.y = rtf(v0.y);
                v1.x = rtf(v1.x); v1.y = rtf(v1.y);
            }
            *(float2*)(Cb + o0) = v0;
            *(float2*)(Cb + o1) = v1;
        }
    }
}

// ===========================================================================
// Row softmax over 4096 columns; output rounded to tf32 (feeds PV GEMM).
// ===========================================================================
__global__ void softmax_kernel(float* __restrict__ s)
{
    const long row = blockIdx.x;
    float* p = s + row * (long)NSP;
    const int tid = threadIdx.x;

    __shared__ float buf[NSP];
    __shared__ float red[256];

    float m = -1e30f;
    for (int i = tid * 4; i < NSP; i += 1024) {
        float4 v = *(const float4*)(p + i);
        *(float4*)(buf + i) = v;
        m = fmaxf(m, fmaxf(fmaxf(v.x, v.y), fmaxf(v.z, v.w)));
    }
    red[tid] = m;
    __syncthreads();
    for (int o = 128; o > 0; o >>= 1) {
        if (tid < o) red[tid] = fmaxf(red[tid], red[tid + o]);
        __syncthreads();
    }
    m = red[0];
    __syncthreads();

    float sum = 0.f;
    for (int i = tid * 4; i < NSP; i += 1024) {
        float4 v = *(const float4*)(buf + i);
        v.x = __expf(v.x - m);
        v.y = __expf(v.y - m);
        v.z = __expf(v.z - m);
        v.w = __expf(v.w - m);
        *(float4*)(buf + i) = v;
        sum += v.x + v.y + v.z + v.w;
    }
    red[tid] = sum;
    __syncthreads();
    for (int o = 128; o > 0; o >>= 1) {
        if (tid < o) red[tid] += red[tid + o];
        __syncthreads();
    }
    const float inv = 1.f / red[0];

    for (int i = tid * 4; i < NSP; i += 1024) {
        float4 v = *(const float4*)(buf + i);
        v.x = rtf(v.x * inv); v.y = rtf(v.y * inv);
        v.z = rtf(v.z * inv); v.w = rtf(v.w * inv);
        *(float4*)(p + i) = v;
    }
}

// ===========================================================================
extern "C" void kernel_launch(void* const* d_in, const int* in_sizes, int n_in,
                              void* d_out, int out_size)
{
    const float* x     = (const float*)d_in[0];
    const float* gamma = (const float*)d_in[1];
    const float* beta  = (const float*)d_in[2];
    const float* wq    = (const float*)d_in[3];
    const float* bq    = (const float*)d_in[4];
    const float* wk    = (const float*)d_in[5];
    const float* bk    = (const float*)d_in[6];
    const float* wv    = (const float*)d_in[7];
    const float* bv    = (const float*)d_in[8];
    const float* wp    = (const float*)d_in[9];
    const float* bp    = (const float*)d_in[10];
    float* out = (float*)d_out;

    float *pht, *pq, *pk, *pv, *po, *ps, *pw, *pmu, *prs;
    cudaGetSymbolAddress((void**)&pht, g_ht);
    cudaGetSymbolAddress((void**)&pq,  g_q);
    cudaGetSymbolAddress((void**)&pk,  g_k);
    cudaGetSymbolAddress((void**)&pv,  g_v);
    cudaGetSymbolAddress((void**)&po,  g_o);
    cudaGetSymbolAddress((void**)&ps,  g_s);
    cudaGetSymbolAddress((void**)&pw,  g_w);
    cudaGetSymbolAddress((void**)&pmu, g_mu);
    cudaGetSymbolAddress((void**)&prs, g_rsd);

    cudaFuncSetAttribute(tgemm<true>,  cudaFuncAttributeMaxDynamicSharedMemorySize,
                         TG_SMEM_BYTES);
    cudaFuncSetAttribute(tgemm<false>, cudaFuncAttributeMaxDynamicSharedMemorySize,
                         TG_SMEM_BYTES);

    const int WN = CCH * CCH;           // 262144
    float* rwq = pw;
    float* rwk = pw + WN;
    float* rwv = pw + 2 * WN;
    float* rwp = pw + 3 * WN;

    // 0) tf32-round the weight matrices
    round_kernel<<<WN / 1024, 256>>>(wq, rwq, WN);
    round_kernel<<<WN / 1024, 256>>>(wk, rwk, WN);
    round_kernel<<<WN / 1024, 256>>>(wv, rwv, WN);
    round_kernel<<<WN / 1024, 256>>>(wp, rwp, WN);

    // 1) GroupNorm stats
    gn_stats<<<BATCH * GROUPS, 256>>>(x, pmu, prs);

    // 2) fused normalize + transpose -> h_t [N,C] (tf32)
    dim3 gT(NSP / 32, CCH / 32, BATCH);
    ntrans_kernel<<<gT, dim3(32, 8)>>>(x, gamma, beta, pmu, prs, pht);

    // 3) q_t[i,o] = sum_c h_t[i,c] wq[o,c] + bq[o]   (M=NSP, N=CCH)
    dim3 gNC(CCH / 128, NSP / 128, BATCH);   // (4, 32, 4)
    tgemm<true><<<gNC, 128, TG_SMEM_BYTES>>>(pht, rwq, pq, CCH, CCH, CCH,
                                             CN, 0, CN, 0,
                                             CCH, 1.f, nullptr, bq, nullptr);
    tgemm<true><<<gNC, 128, TG_SMEM_BYTES>>>(pht, rwk, pk, CCH, CCH, CCH,
                                             CN, 0, CN, 0,
                                             CCH, 1.f, nullptr, bk, nullptr);

    // 4) v[c,j] = sum_c' wv[c,c'] h_t[j,c'] + bv[c]  (M=CCH, N=NSP)
    dim3 gCN(NSP / 128, CCH / 128, BATCH);   // (32, 4, 4)
    tgemm<true><<<gCN, 128, TG_SMEM_BYTES>>>(rwv, pht, pv, CCH, CCH, NSP,
                                             0, CN, CN, 0,
                                             CCH, 1.f, bv, nullptr, nullptr);

    // 5) scores S[i,j] = scale * sum_c q_t[i,c] k_t[j,c]  (M=N=NSP)
    const float scale = 0.04419417382415922f;  // 512^-0.5
    dim3 gSS(NSP / 128, NSP / 128, BATCH);   // (32, 32, 4)
    tgemm<false><<<gSS, 128, TG_SMEM_BYTES>>>(pq, pk, ps, CCH, CCH, NSP,
                                              CN, CN, NNL, 0,
                                              CCH, scale, nullptr, nullptr, nullptr);

    // 6) softmax over keys (rows of S), rounds output to tf32
    softmax_kernel<<<BATCH * NSP, 256>>>(ps);

    // 7) O_t[i,c] = sum_j P[i,j] v[c,j]   (M=NSP, N=CCH, K=NSP)
    tgemm<true><<<gNC, 128, TG_SMEM_BYTES>>>(ps, pv, po, NSP, NSP, CCH,
                                             NNL, CN, CN, 0,
                                             NSP, 1.f, nullptr, nullptr, nullptr);

    // 8) out[o,n] = sum_c wp[o,c] O_t[n,c] + bp[o] + x[o,n]  (M=CCH, N=NSP)
    tgemm<false><<<gCN, 128, TG_SMEM_BYTES>>>(rwp, po, out, CCH, CCH, NSP,
                                              0, CN, CN, CN,
                                              CCH, 1.f, bp, nullptr, x);
}